// round 10
// baseline (speedup 1.0000x reference)
#include <cuda_runtime.h>
#include <cstdint>

// ---------------- problem constants ----------------
#define BB 8
#define CC 256
#define HHW 6400          // 80*80
#define GROUPS 32
#define CPG 8
#define TOTAL (BB*CC*HHW) // 13,107,200
#define PW 82
#define PHW (PW*PW)       // 6724
#define KTOT (CC*9)       // 2304
#define NCHUNK 72         // K chunks of 32, tap-major: k = t*256 + ci
#define NSTG 3            // cp.async pipeline stages

// ---------------- scratch (__device__ globals; no allocation) ----------------
// channels-last padded input: g_pad[b][py][px][ci], tf32-rounded
__device__ float g_pad[(size_t)BB * PHW * CC];
// weights fragment-linear per (half, chunk): 2*72*4096 floats
__device__ float g_wtF[(size_t)2 * NCHUNK * 4096];
__device__ float g_h[(size_t)TOTAL];         // conv output, NCHW
__device__ float g_gate[BB*HHW];
__device__ float g_mean[BB*GROUPS];
__device__ float g_rstd[BB*GROUPS];

// ---------------- helpers ----------------
__device__ __forceinline__ float f2tf32(float v){
    uint32_t r; asm("cvt.rna.tf32.f32 %0, %1;" : "=r"(r) : "f"(v));
    return __uint_as_float(r);
}
__device__ __forceinline__ void mma_tf32(float* d, const uint32_t* a, const uint32_t* b){
    asm volatile(
        "mma.sync.aligned.m16n8k8.row.col.f32.tf32.tf32.f32 "
        "{%0,%1,%2,%3}, {%4,%5,%6,%7}, {%8,%9}, {%0,%1,%2,%3};"
        : "+f"(d[0]), "+f"(d[1]), "+f"(d[2]), "+f"(d[3])
        : "r"(a[0]), "r"(a[1]), "r"(a[2]), "r"(a[3]), "r"(b[0]), "r"(b[1]));
}
__device__ __forceinline__ void cp_async16(uint32_t dst, const void* src){
    asm volatile("cp.async.cg.shared.global [%0], [%1], 16;" :: "r"(dst), "l"(src));
}

// ---------------- prep kernels ----------------
// weights -> fragment-linear per (half, chunk): float2 entry
//   i = ((half*NCHUNK + ch)*64 + q)*32 + lane, q = nt*4 + kt
//   co = half*128 + nt*8 + lane/4 ; klocal = kt*8 + lane%4 (and +4)
//   tap t = ch>>3, ci = (ch&7)*32 + klocal ; src w[co][ci][t]
__global__ __launch_bounds__(256)
void prep_w_kernel(const float* __restrict__ w, float2* __restrict__ wtF2)
{
    int i = blockIdx.x * 256 + threadIdx.x;
    if (i >= 2 * NCHUNK * 2048) return;
    int lane = i & 31;
    int q    = (i >> 5) & 63;
    int rest = i >> 11;
    int ch   = rest % NCHUNK;
    int half = rest / NCHUNK;
    int nt = q >> 2, kt = q & 3;
    int co = half * 128 + nt * 8 + (lane >> 2);
    int t  = ch >> 3;
    int ci0 = (ch & 7) * 32;
    int k0 = ci0 + kt * 8 + (lane & 3);
    float2 v;
    v.x = f2tf32(w[((size_t)co * CC + k0) * 9 + t]);
    v.y = f2tf32(w[((size_t)co * CC + k0 + 4) * 9 + t]);
    wtF2[i] = v;
}

// zero the 1-pixel border ring of g_pad (channels-last), once
__global__ __launch_bounds__(256)
void zero_border_kernel(float* __restrict__ pad)
{
    int pos = blockIdx.x;       // 0..81
    int s   = blockIdx.y;       // strip
    int b   = blockIdx.z;
    int py, px;
    if (s == 0)      { py = 0;   px = pos; }
    else if (s == 1) { py = 81;  px = pos; }
    else if (s == 2) { py = pos; px = 0;   }
    else             { py = pos; px = 81;  }
    pad[((size_t)b * PHW + py * PW + px) * CC + threadIdx.x] = 0.0f;
}

// NCHW x -> channels-last padded tf32 (smem transpose, one image row x 32ci per block)
__global__ __launch_bounds__(256)
void pad_x_t_kernel(const float* __restrict__ x, float* __restrict__ pad)
{
    __shared__ float t[32 * 81];
    const int y   = blockIdx.x;       // 0..79
    const int cB  = blockIdx.y;       // 0..7  (32-ci slab)
    const int b   = blockIdx.z;
    const int tid = threadIdx.x;
    for (int idx = tid; idx < 2560; idx += 256) {
        int px = idx % 80, cc = idx / 80;
        t[cc * 81 + px] = x[((size_t)(b * CC + cB * 32 + cc) * 80 + y) * 80 + px];
    }
    __syncthreads();
    for (int idx = tid; idx < 2560; idx += 256) {
        int cc = idx & 31, px = idx >> 5;
        pad[((size_t)b * PHW + (y + 1) * PW + (px + 1)) * CC + cB * 32 + cc] =
            f2tf32(t[cc * 81 + px]);
    }
}

// NCHW h -> GN affine + ReLU -> channels-last padded tf32
__global__ __launch_bounds__(256)
void pad_h_t_kernel(const float* __restrict__ h, const float* __restrict__ mean,
                    const float* __restrict__ rstd, const float* __restrict__ gw,
                    const float* __restrict__ gb, float* __restrict__ pad)
{
    __shared__ float t[32 * 81];
    __shared__ float ssc[32], ssb[32];
    const int y   = blockIdx.x;
    const int cB  = blockIdx.y;
    const int b   = blockIdx.z;
    const int tid = threadIdx.x;
    if (tid < 32) {
        int ci = cB * 32 + tid;
        int bg = b * GROUPS + ci / CPG;
        float sc = rstd[bg] * gw[ci];
        ssc[tid] = sc;
        ssb[tid] = fmaf(-mean[bg], sc, gb[ci]);
    }
    for (int idx = tid; idx < 2560; idx += 256) {
        int px = idx % 80, cc = idx / 80;
        t[cc * 81 + px] = h[((size_t)(b * CC + cB * 32 + cc) * 80 + y) * 80 + px];
    }
    __syncthreads();
    for (int idx = tid; idx < 2560; idx += 256) {
        int cc = idx & 31, px = idx >> 5;
        float v = fmaxf(fmaf(t[cc * 81 + px], ssc[cc], ssb[cc]), 0.0f);
        pad[((size_t)b * PHW + (y + 1) * PW + (px + 1)) * CC + cB * 32 + cc] =
            f2tf32(v);
    }
}

// ---------------- HMMA tf32 implicit-GEMM conv, cp.async pipelined ----------------
// CTA: 128 thr = 4 warps (2M x 2N), warp tile 64px x 64co. CTA tile 128px x 128co.
// Pixel tile 16 rows x 8 cols. K chunk = 32 (one tap, 32 ci, contiguous in gmem).
// smem: 3 stages x (A 16KB swizzled row-major + B 16KB fragment-linear).
__global__ __launch_bounds__(128, 2)
void conv_mma_kernel(const float* __restrict__ pad, const float* __restrict__ wtF,
                     float* __restrict__ out)
{
    extern __shared__ float dsm[];           // [3][8192]: A at +0, B at +4096
    __shared__ int s_toff[9];

    const int tid  = threadIdx.x;
    const int lane = tid & 31;
    const int warp = tid >> 5;               // 0..3
    const int mw = warp >> 1;                // 0..1
    const int nw = warp & 1;                 // 0..1

    if (tid < 9) s_toff[tid] = ((tid / 3) * PW + (tid % 3)) * CC;

    const int PX0 = blockIdx.x * 8;
    const int PY0 = blockIdx.y * 16;
    const int bz  = blockIdx.z;
    const int b   = bz >> 1;
    const int half = bz & 1;
    const int co0  = half * 128;

    // producer: thread owns pixel index = tid (py = tid>>3, px = tid&7)
    const int gy = PY0 + (tid >> 3);
    const int gx = PX0 + (tid & 7);
    const float* Apix  = pad + ((size_t)b * PHW + (size_t)gy * PW + gx) * CC;
    const float* Bsrc0 = wtF + (size_t)half * NCHUNK * 4096;
    const int sw = tid & 7;                  // A swizzle key for this pixel row
    const uint32_t smem0 = (uint32_t)__cvta_generic_to_shared(dsm);

    float acc[4][8][4];
#pragma unroll
    for (int mi = 0; mi < 4; mi++)
#pragma unroll
        for (int ni = 0; ni < 8; ni++)
#pragma unroll
            for (int q = 0; q < 4; q++) acc[mi][ni][q] = 0.0f;

    __syncthreads();   // s_toff ready

#define ISSUE(CH) do {                                                          \
        const int _ch = (CH);                                                   \
        const int _st = _ch % NSTG;                                             \
        const float* _as = Apix + s_toff[_ch >> 3] + ((_ch & 7) << 5);          \
        uint32_t _ad = smem0 + _st * 32768 + tid * 128;                         \
        _Pragma("unroll")                                                       \
        for (int _ks = 0; _ks < 8; _ks++)                                       \
            cp_async16(_ad + ((_ks ^ sw) << 4), _as + _ks * 4);                 \
        const float* _bs = Bsrc0 + (size_t)_ch * 4096 + tid * 32;               \
        uint32_t _bd = smem0 + _st * 32768 + 16384 + tid * 128;                 \
        _Pragma("unroll")                                                       \
        for (int _j = 0; _j < 8; _j++)                                          \
            cp_async16(_bd + _j * 16, _bs + _j * 4);                            \
        asm volatile("cp.async.commit_group;" ::: "memory");                    \
    } while (0)

    // prologue: stages 0,1
    ISSUE(0);
    ISSUE(1);

    const int r  = lane >> 2;      // 0..7
    const int cq = lane & 3;       // 0..3

    for (int ch = 0; ch < NCHUNK; ch++) {
        if (ch < NCHUNK - 1)
            asm volatile("cp.async.wait_group 1;" ::: "memory");
        else
            asm volatile("cp.async.wait_group 0;" ::: "memory");
        __syncthreads();

        const int st = ch % NSTG;
        const uint32_t* As = (const uint32_t*)(dsm + st * 8192);
        const uint2*    Bs = (const uint2*)  (dsm + st * 8192 + 4096);

#pragma unroll
        for (int kt = 0; kt < 4; kt++) {
            const int s0 = (((kt * 2)     ^ r) << 2) + cq;
            const int s1 = (((kt * 2 + 1) ^ r) << 2) + cq;
            uint32_t af[4][4];
            uint2 bf[8];
#pragma unroll
            for (int mi = 0; mi < 4; mi++) {
                const int rowb = (mw * 64 + mi * 16 + r) * 32;
                af[mi][0] = As[rowb + s0];
                af[mi][1] = As[rowb + 256 + s0];
                af[mi][2] = As[rowb + s1];
                af[mi][3] = As[rowb + 256 + s1];
            }
#pragma unroll
            for (int ni = 0; ni < 8; ni++)
                bf[ni] = Bs[((nw * 8 + ni) * 4 + kt) * 32 + lane];
#pragma unroll
            for (int mi = 0; mi < 4; mi++)
#pragma unroll
                for (int ni = 0; ni < 8; ni++)
                    mma_tf32(acc[mi][ni], af[mi], (const uint32_t*)&bf[ni]);
        }

        if (ch + 2 < NCHUNK) ISSUE(ch + 2);
        // buffer (ch+2)%3 was consumed at iter ch-1; all threads passed this
        // iteration's __syncthreads after completing consume(ch-1) -> safe.
    }
#undef ISSUE

    // ---- epilogue: acc -> out[b][co][py][px] (NCHW) ----
    // d-frag: d0=D[m][c], d1=D[m][c+1], d2=D[m+8][c], d3=D[m+8][c+1]
    const int r0 = lane >> 2;
    const int c0 = 2 * (lane & 3);
#pragma unroll
    for (int mi = 0; mi < 4; mi++) {
        int gpy = PY0 + mw * 8 + mi * 2;
        int gxx = PX0 + r0;
#pragma unroll
        for (int ni = 0; ni < 8; ni++) {
            int co_c = co0 + nw * 64 + ni * 8 + c0;
            float* p = out + ((size_t)b * CC + co_c) * HHW + gpy * 80 + gxx;
            p[0]        = acc[mi][ni][0];
            p[HHW]      = acc[mi][ni][1];
            p[80]       = acc[mi][ni][2];
            p[HHW + 80] = acc[mi][ni][3];
        }
    }
}

// ---------------- GroupNorm stats: one block per (b, group), float4 ----------------
__global__ __launch_bounds__(256)
void gn_stats_kernel(const float* __restrict__ in, float* __restrict__ mean,
                     float* __restrict__ rstd)
{
    const int bg = blockIdx.x;
    const float4* p = (const float4*)(in + (size_t)bg * (CPG * HHW));
    const int tid = threadIdx.x;
    float s = 0.0f, ss = 0.0f;
#pragma unroll 4
    for (int i = tid; i < CPG * HHW / 4; i += 256) {
        float4 v = p[i];
        s += v.x + v.y + v.z + v.w;
        ss = fmaf(v.x, v.x, ss); ss = fmaf(v.y, v.y, ss);
        ss = fmaf(v.z, v.z, ss); ss = fmaf(v.w, v.w, ss);
    }
    __shared__ float sb0[8], sb1[8];
#pragma unroll
    for (int o = 16; o; o >>= 1) {
        s  += __shfl_down_sync(0xffffffffu, s, o);
        ss += __shfl_down_sync(0xffffffffu, ss, o);
    }
    if ((tid & 31) == 0) { sb0[tid >> 5] = s; sb1[tid >> 5] = ss; }
    __syncthreads();
    if (tid == 0) {
        s = 0.0f; ss = 0.0f;
#pragma unroll
        for (int i = 0; i < 8; i++) { s += sb0[i]; ss += sb1[i]; }
        const float inv_n = 1.0f / (float)(CPG * HHW);
        float m = s * inv_n;
        float var = ss * inv_n - m * m;
        mean[bg] = m;
        rstd[bg] = rsqrtf(var + 1e-5f);
    }
}

// ---------------- spatial gate ----------------
__global__ __launch_bounds__(256)
void gate_kernel(const float* __restrict__ x, const float* __restrict__ gw,
                 const float* __restrict__ gb, float* __restrict__ gate)
{
    __shared__ float wsm[CC];
    const int tid = threadIdx.x;
    wsm[tid] = gw[tid];
    __syncthreads();
    const int p = blockIdx.x * 256 + tid;
    const int b = p / HHW, pp = p - b * HHW;
    const float* xb = x + (size_t)b * CC * HHW + pp;
    float s = gb[0];
#pragma unroll 8
    for (int c = 0; c < CC; c++) s = fmaf(xb[(size_t)c * HHW], wsm[c], s);
    gate[p] = fmaxf(tanhf(s), 0.0f);
}

// ---------------- final: out = relu(gn2(h)*gate + x) ----------------
__global__ __launch_bounds__(256)
void final_kernel(const float* __restrict__ h, const float* __restrict__ mean,
                  const float* __restrict__ rstd, const float* __restrict__ w,
                  const float* __restrict__ bias, const float* __restrict__ gate,
                  const float* __restrict__ x, float* __restrict__ out)
{
    int idx = blockIdx.x * blockDim.x + threadIdx.x;
    if (idx >= TOTAL / 4) return;
    const int c  = (idx / (HHW / 4)) % CC;
    const int b  = idx / ((HHW / 4) * CC);
    const int bg = b * GROUPS + c / CPG;
    const float sc = rstd[bg] * w[c];
    const float sb = fmaf(-mean[bg], sc, bias[c]);
    const int p4 = idx % (HHW / 4);
    const float4 g4 = ((const float4*)(gate + (size_t)b * HHW))[p4];
    float4 hv = ((const float4*)h)[idx];
    float4 xv = ((const float4*)x)[idx];
    float4 o;
    o.x = fmaxf(fmaf(fmaf(hv.x, sc, sb), g4.x, xv.x), 0.0f);
    o.y = fmaxf(fmaf(fmaf(hv.y, sc, sb), g4.y, xv.y), 0.0f);
    o.z = fmaxf(fmaf(fmaf(hv.z, sc, sb), g4.z, xv.z), 0.0f);
    o.w = fmaxf(fmaf(fmaf(hv.w, sc, sb), g4.w, xv.w), 0.0f);
    ((float4*)out)[idx] = o;
}

// ---------------- launch ----------------
extern "C" void kernel_launch(void* const* d_in, const int* in_sizes, int n_in,
                              void* d_out, int out_size)
{
    const float* x    = (const float*)d_in[0];
    const float* w1   = (const float*)d_in[1];
    const float* gn1w = (const float*)d_in[2];
    const float* gn1b = (const float*)d_in[3];
    const float* w2   = (const float*)d_in[4];
    const float* gn2w = (const float*)d_in[5];
    const float* gn2b = (const float*)d_in[6];
    const float* gw   = (const float*)d_in[7];
    const float* gb   = (const float*)d_in[8];
    float* out = (float*)d_out;

    float *padb, *wtb, *hb, *gateb, *meanb, *rstdb;
    cudaGetSymbolAddress((void**)&padb,  g_pad);
    cudaGetSymbolAddress((void**)&wtb,   g_wtF);
    cudaGetSymbolAddress((void**)&hb,    g_h);
    cudaGetSymbolAddress((void**)&gateb, g_gate);
    cudaGetSymbolAddress((void**)&meanb, g_mean);
    cudaGetSymbolAddress((void**)&rstdb, g_rstd);

    const int SMEM = NSTG * 32768;   // 96 KB
    cudaFuncSetAttribute(conv_mma_kernel,
                         cudaFuncAttributeMaxDynamicSharedMemorySize, SMEM);

    const int wN  = 2 * NCHUNK * 2048;
    const int wBl = (wN + 255) / 256;
    const int ewBl = (TOTAL / 4 + 255) / 256;
    dim3 cgrid(10, 5, BB * 2);        // px-tiles x py-tiles x (b, co-half)
    dim3 pgrid(80, 8, BB);            // y x ci-slab x b
    dim3 zgrid(82, 4, BB);            // border strips

    // one-time-ish prep (cheap, graph-replayed each run: deterministic)
    zero_border_kernel<<<zgrid, 256>>>(padb);
    prep_w_kernel<<<wBl, 256>>>(w1, (float2*)wtb);
    pad_x_t_kernel<<<pgrid, 256>>>(x, padb);
    // conv1 -> g_h (NCHW)
    conv_mma_kernel<<<cgrid, 128, SMEM>>>(padb, wtb, hb);
    // GN1 stats -> padded relu(gn1(h)) channels-last; prep w2
    gn_stats_kernel<<<BB * GROUPS, 256>>>(hb, meanb, rstdb);
    pad_h_t_kernel<<<pgrid, 256>>>(hb, meanb, rstdb, gn1w, gn1b, padb);
    prep_w_kernel<<<wBl, 256>>>(w2, (float2*)wtb);
    // conv2 -> g_h, GN2 stats
    conv_mma_kernel<<<cgrid, 128, SMEM>>>(padb, wtb, hb);
    gn_stats_kernel<<<BB * GROUPS, 256>>>(hb, meanb, rstdb);
    // gate + fused epilogue
    gate_kernel<<<(BB * HHW) / 256, 256>>>(x, gw, gb, gateb);
    final_kernel<<<ewBl, 256>>>(hb, meanb, rstdb, gn2w, gn2b, gateb, x, out);
}

// round 11
// speedup vs baseline: 1.2586x; 1.2586x over previous
#include <cuda_runtime.h>
#include <cstdint>

// ---------------- problem constants ----------------
#define BB 8
#define CC 256
#define HHW 6400          // 80*80
#define GROUPS 32
#define CPG 8
#define TOTAL (BB*CC*HHW) // 13,107,200
#define PW 82
#define PHW (PW*PW)       // 6724
#define KTOT (CC*9)       // 2304
#define NCHUNK 72         // K chunks of 32, tap-major: k = t*256 + ci
#define NSTG 3            // cp.async pipeline stages

// ---------------- scratch (__device__ globals; no allocation) ----------------
__device__ float g_pad[(size_t)BB * PHW * CC];       // channels-last padded input
__device__ float g_wtF[(size_t)2 * NCHUNK * 4096];   // weights fragment-linear
__device__ float g_h[(size_t)TOTAL];                 // conv output, NCHW
__device__ float g_gate[BB*HHW];
__device__ float g_mean[BB*GROUPS];
__device__ float g_rstd[BB*GROUPS];

// ---------------- helpers ----------------
__device__ __forceinline__ float f2tf32(float v){
    uint32_t r; asm("cvt.rna.tf32.f32 %0, %1;" : "=r"(r) : "f"(v));
    return __uint_as_float(r);
}
__device__ __forceinline__ void mma_tf32(float* d, const uint32_t* a, const uint32_t* b){
    asm volatile(
        "mma.sync.aligned.m16n8k8.row.col.f32.tf32.tf32.f32 "
        "{%0,%1,%2,%3}, {%4,%5,%6,%7}, {%8,%9}, {%0,%1,%2,%3};"
        : "+f"(d[0]), "+f"(d[1]), "+f"(d[2]), "+f"(d[3])
        : "r"(a[0]), "r"(a[1]), "r"(a[2]), "r"(a[3]), "r"(b[0]), "r"(b[1]));
}
__device__ __forceinline__ void cp_async16(uint32_t dst, const void* src){
    asm volatile("cp.async.cg.shared.global [%0], [%1], 16;" :: "r"(dst), "l"(src));
}

// ---------------- prep kernels (unchanged layouts from R10) ----------------
// weights -> fragment-linear per (half, chunk); q = nt*4+kt, nt 0..15
__global__ __launch_bounds__(256)
void prep_w_kernel(const float* __restrict__ w, float2* __restrict__ wtF2)
{
    int i = blockIdx.x * 256 + threadIdx.x;
    if (i >= 2 * NCHUNK * 2048) return;
    int lane = i & 31;
    int q    = (i >> 5) & 63;
    int rest = i >> 11;
    int ch   = rest % NCHUNK;
    int half = rest / NCHUNK;
    int nt = q >> 2, kt = q & 3;
    int co = half * 128 + nt * 8 + (lane >> 2);
    int t  = ch >> 3;
    int k0 = (ch & 7) * 32 + kt * 8 + (lane & 3);
    float2 v;
    v.x = f2tf32(w[((size_t)co * CC + k0) * 9 + t]);
    v.y = f2tf32(w[((size_t)co * CC + k0 + 4) * 9 + t]);
    wtF2[i] = v;
}

__global__ __launch_bounds__(256)
void zero_border_kernel(float* __restrict__ pad)
{
    int pos = blockIdx.x;       // 0..81
    int s   = blockIdx.y;
    int b   = blockIdx.z;
    int py, px;
    if (s == 0)      { py = 0;   px = pos; }
    else if (s == 1) { py = 81;  px = pos; }
    else if (s == 2) { py = pos; px = 0;   }
    else             { py = pos; px = 81;  }
    pad[((size_t)b * PHW + py * PW + px) * CC + threadIdx.x] = 0.0f;
}

__global__ __launch_bounds__(256)
void pad_x_t_kernel(const float* __restrict__ x, float* __restrict__ pad)
{
    __shared__ float t[32 * 81];
    const int y   = blockIdx.x;
    const int cB  = blockIdx.y;
    const int b   = blockIdx.z;
    const int tid = threadIdx.x;
    for (int idx = tid; idx < 2560; idx += 256) {
        int px = idx % 80, cc = idx / 80;
        t[cc * 81 + px] = x[((size_t)(b * CC + cB * 32 + cc) * 80 + y) * 80 + px];
    }
    __syncthreads();
    for (int idx = tid; idx < 2560; idx += 256) {
        int cc = idx & 31, px = idx >> 5;
        pad[((size_t)b * PHW + (y + 1) * PW + (px + 1)) * CC + cB * 32 + cc] =
            f2tf32(t[cc * 81 + px]);
    }
}

__global__ __launch_bounds__(256)
void pad_h_t_kernel(const float* __restrict__ h, const float* __restrict__ mean,
                    const float* __restrict__ rstd, const float* __restrict__ gw,
                    const float* __restrict__ gb, float* __restrict__ pad)
{
    __shared__ float t[32 * 81];
    __shared__ float ssc[32], ssb[32];
    const int y   = blockIdx.x;
    const int cB  = blockIdx.y;
    const int b   = blockIdx.z;
    const int tid = threadIdx.x;
    if (tid < 32) {
        int ci = cB * 32 + tid;
        int bg = b * GROUPS + ci / CPG;
        float sc = rstd[bg] * gw[ci];
        ssc[tid] = sc;
        ssb[tid] = fmaf(-mean[bg], sc, gb[ci]);
    }
    for (int idx = tid; idx < 2560; idx += 256) {
        int px = idx % 80, cc = idx / 80;
        t[cc * 81 + px] = h[((size_t)(b * CC + cB * 32 + cc) * 80 + y) * 80 + px];
    }
    __syncthreads();
    for (int idx = tid; idx < 2560; idx += 256) {
        int cc = idx & 31, px = idx >> 5;
        float v = fmaxf(fmaf(t[cc * 81 + px], ssc[cc], ssb[cc]), 0.0f);
        pad[((size_t)b * PHW + (y + 1) * PW + (px + 1)) * CC + cB * 32 + cc] =
            f2tf32(v);
    }
}

// ---------------- HMMA tf32 implicit-GEMM conv, cp.async, 256-thr CTA ----------------
// 8 warps (2M x 4N), warp tile 64px x 32co. CTA tile 128px x 128co.
// Pixel tile 16 rows x 8 cols. K chunk = 32 (one tap, 32 contiguous ci).
// smem: 3 stages x (A 16KB swizzled row-major + B 16KB fragment-linear) = 96KB.
__global__ __launch_bounds__(256, 2)
void conv_mma_kernel(const float* __restrict__ pad, const float* __restrict__ wtF,
                     float* __restrict__ out)
{
    extern __shared__ float dsm[];           // [3][8192]: A at +0, B at +4096 floats
    __shared__ int s_toff[9];

    const int tid  = threadIdx.x;
    const int lane = tid & 31;
    const int warp = tid >> 5;               // 0..7
    const int mw = warp >> 2;                // 0..1
    const int nw = warp & 3;                 // 0..3

    if (tid < 9) s_toff[tid] = ((tid / 3) * PW + (tid % 3)) * CC;

    const int PX0 = blockIdx.x * 8;
    const int PY0 = blockIdx.y * 16;
    const int bz  = blockIdx.z;
    const int b   = bz >> 1;
    const int half = bz & 1;
    const int co0  = half * 128;

    // producer: thread covers pixel pxP = tid>>1, k-half segH = tid&1
    const int pxP  = tid >> 1;
    const int segH = tid & 1;
    const int gy = PY0 + (pxP >> 3);
    const int gx = PX0 + (pxP & 7);
    const float* Apix  = pad + ((size_t)b * PHW + (size_t)gy * PW + gx) * CC;
    const float* Bsrc0 = wtF + (size_t)half * NCHUNK * 4096;
    const int swP = pxP & 7;
    const uint32_t smem0 = (uint32_t)__cvta_generic_to_shared(dsm);

    float acc[4][4][4];
#pragma unroll
    for (int mi = 0; mi < 4; mi++)
#pragma unroll
        for (int ni = 0; ni < 4; ni++)
#pragma unroll
            for (int q = 0; q < 4; q++) acc[mi][ni][q] = 0.0f;

    __syncthreads();   // s_toff ready

#define ISSUE(CH) do {                                                          \
        const int _ch = (CH);                                                   \
        const int _st = _ch % NSTG;                                             \
        const float* _as = Apix + s_toff[_ch >> 3] + ((_ch & 7) << 5);          \
        uint32_t _ad = smem0 + _st * 32768 + pxP * 128;                         \
        _Pragma("unroll")                                                       \
        for (int _j = 0; _j < 4; _j++) {                                        \
            int _ks = segH * 4 + _j;                                            \
            cp_async16(_ad + ((_ks ^ swP) << 4), _as + _ks * 4);                \
        }                                                                       \
        const float* _bs = Bsrc0 + (size_t)_ch * 4096;                          \
        uint32_t _bd = smem0 + _st * 32768 + 16384;                             \
        _Pragma("unroll")                                                       \
        for (int _j = 0; _j < 4; _j++) {                                        \
            int _u = tid + _j * 256;                                            \
            cp_async16(_bd + _u * 16, _bs + _u * 4);                            \
        }                                                                       \
        asm volatile("cp.async.commit_group;" ::: "memory");                    \
    } while (0)

    // prologue: stages 0,1
    ISSUE(0);
    ISSUE(1);

    const int r  = lane >> 2;      // 0..7
    const int cq = lane & 3;       // 0..3

    for (int ch = 0; ch < NCHUNK; ch++) {
        if (ch < NCHUNK - 1)
            asm volatile("cp.async.wait_group 1;" ::: "memory");
        else
            asm volatile("cp.async.wait_group 0;" ::: "memory");
        __syncthreads();

        const int st = ch % NSTG;
        const uint32_t* As = (const uint32_t*)(dsm + st * 8192);
        const uint2*    Bs = (const uint2*)  (dsm + st * 8192 + 4096);

#pragma unroll
        for (int kt = 0; kt < 4; kt++) {
            const int s0 = (((kt * 2)     ^ r) << 2) + cq;
            const int s1 = (((kt * 2 + 1) ^ r) << 2) + cq;
            uint32_t af[4][4];
            uint2 bf[4];
#pragma unroll
            for (int mi = 0; mi < 4; mi++) {
                const int rowb = (mw * 64 + mi * 16 + r) * 32;
                af[mi][0] = As[rowb + s0];
                af[mi][1] = As[rowb + 256 + s0];
                af[mi][2] = As[rowb + s1];
                af[mi][3] = As[rowb + 256 + s1];
            }
#pragma unroll
            for (int ni = 0; ni < 4; ni++)
                bf[ni] = Bs[(((nw * 4 + ni) * 4) + kt) * 32 + lane];
#pragma unroll
            for (int mi = 0; mi < 4; mi++)
#pragma unroll
                for (int ni = 0; ni < 4; ni++)
                    mma_tf32(acc[mi][ni], af[mi], (const uint32_t*)&bf[ni]);
        }

        if (ch + 2 < NCHUNK) ISSUE(ch + 2);
    }
#undef ISSUE

    // ---- epilogue: acc -> out[b][co][py][px] (NCHW) ----
    // d-frag: d0=D[m][c], d1=D[m][c+1], d2=D[m+8][c], d3=D[m+8][c+1]
    // m = mw*64 + mi*16 + r0  ->  py = mw*8 + mi*2, px = r0; m+8 -> py+1
    const int r0 = lane >> 2;
    const int c0 = 2 * (lane & 3);
#pragma unroll
    for (int mi = 0; mi < 4; mi++) {
        int gpy = PY0 + mw * 8 + mi * 2;
        int gxx = PX0 + r0;
#pragma unroll
        for (int ni = 0; ni < 4; ni++) {
            int co_c = co0 + nw * 32 + ni * 8 + c0;
            float* p = out + ((size_t)b * CC + co_c) * HHW + gpy * 80 + gxx;
            p[0]        = acc[mi][ni][0];
            p[HHW]      = acc[mi][ni][1];
            p[80]       = acc[mi][ni][2];
            p[HHW + 80] = acc[mi][ni][3];
        }
    }
}

// ---------------- GroupNorm stats ----------------
__global__ __launch_bounds__(256)
void gn_stats_kernel(const float* __restrict__ in, float* __restrict__ mean,
                     float* __restrict__ rstd)
{
    const int bg = blockIdx.x;
    const float4* p = (const float4*)(in + (size_t)bg * (CPG * HHW));
    const int tid = threadIdx.x;
    float s = 0.0f, ss = 0.0f;
#pragma unroll 4
    for (int i = tid; i < CPG * HHW / 4; i += 256) {
        float4 v = p[i];
        s += v.x + v.y + v.z + v.w;
        ss = fmaf(v.x, v.x, ss); ss = fmaf(v.y, v.y, ss);
        ss = fmaf(v.z, v.z, ss); ss = fmaf(v.w, v.w, ss);
    }
    __shared__ float sb0[8], sb1[8];
#pragma unroll
    for (int o = 16; o; o >>= 1) {
        s  += __shfl_down_sync(0xffffffffu, s, o);
        ss += __shfl_down_sync(0xffffffffu, ss, o);
    }
    if ((tid & 31) == 0) { sb0[tid >> 5] = s; sb1[tid >> 5] = ss; }
    __syncthreads();
    if (tid == 0) {
        s = 0.0f; ss = 0.0f;
#pragma unroll
        for (int i = 0; i < 8; i++) { s += sb0[i]; ss += sb1[i]; }
        const float inv_n = 1.0f / (float)(CPG * HHW);
        float m = s * inv_n;
        float var = ss * inv_n - m * m;
        mean[bg] = m;
        rstd[bg] = rsqrtf(var + 1e-5f);
    }
}

// ---------------- spatial gate ----------------
__global__ __launch_bounds__(256)
void gate_kernel(const float* __restrict__ x, const float* __restrict__ gw,
                 const float* __restrict__ gb, float* __restrict__ gate)
{
    __shared__ float wsm[CC];
    const int tid = threadIdx.x;
    wsm[tid] = gw[tid];
    __syncthreads();
    const int p = blockIdx.x * 256 + tid;
    const int b = p / HHW, pp = p - b * HHW;
    const float* xb = x + (size_t)b * CC * HHW + pp;
    float s = gb[0];
#pragma unroll 8
    for (int c = 0; c < CC; c++) s = fmaf(xb[(size_t)c * HHW], wsm[c], s);
    gate[p] = fmaxf(tanhf(s), 0.0f);
}

// ---------------- final: out = relu(gn2(h)*gate + x) ----------------
__global__ __launch_bounds__(256)
void final_kernel(const float* __restrict__ h, const float* __restrict__ mean,
                  const float* __restrict__ rstd, const float* __restrict__ w,
                  const float* __restrict__ bias, const float* __restrict__ gate,
                  const float* __restrict__ x, float* __restrict__ out)
{
    int idx = blockIdx.x * blockDim.x + threadIdx.x;
    if (idx >= TOTAL / 4) return;
    const int c  = (idx / (HHW / 4)) % CC;
    const int b  = idx / ((HHW / 4) * CC);
    const int bg = b * GROUPS + c / CPG;
    const float sc = rstd[bg] * w[c];
    const float sb = fmaf(-mean[bg], sc, bias[c]);
    const int p4 = idx % (HHW / 4);
    const float4 g4 = ((const float4*)(gate + (size_t)b * HHW))[p4];
    float4 hv = ((const float4*)h)[idx];
    float4 xv = ((const float4*)x)[idx];
    float4 o;
    o.x = fmaxf(fmaf(fmaf(hv.x, sc, sb), g4.x, xv.x), 0.0f);
    o.y = fmaxf(fmaf(fmaf(hv.y, sc, sb), g4.y, xv.y), 0.0f);
    o.z = fmaxf(fmaf(fmaf(hv.z, sc, sb), g4.z, xv.z), 0.0f);
    o.w = fmaxf(fmaf(fmaf(hv.w, sc, sb), g4.w, xv.w), 0.0f);
    ((float4*)out)[idx] = o;
}

// ---------------- launch ----------------
extern "C" void kernel_launch(void* const* d_in, const int* in_sizes, int n_in,
                              void* d_out, int out_size)
{
    const float* x    = (const float*)d_in[0];
    const float* w1   = (const float*)d_in[1];
    const float* gn1w = (const float*)d_in[2];
    const float* gn1b = (const float*)d_in[3];
    const float* w2   = (const float*)d_in[4];
    const float* gn2w = (const float*)d_in[5];
    const float* gn2b = (const float*)d_in[6];
    const float* gw   = (const float*)d_in[7];
    const float* gb   = (const float*)d_in[8];
    float* out = (float*)d_out;

    float *padb, *wtb, *hb, *gateb, *meanb, *rstdb;
    cudaGetSymbolAddress((void**)&padb,  g_pad);
    cudaGetSymbolAddress((void**)&wtb,   g_wtF);
    cudaGetSymbolAddress((void**)&hb,    g_h);
    cudaGetSymbolAddress((void**)&gateb, g_gate);
    cudaGetSymbolAddress((void**)&meanb, g_mean);
    cudaGetSymbolAddress((void**)&rstdb, g_rstd);

    const int SMEM = NSTG * 32768;   // 96 KB
    cudaFuncSetAttribute(conv_mma_kernel,
                         cudaFuncAttributeMaxDynamicSharedMemorySize, SMEM);

    const int wN  = 2 * NCHUNK * 2048;
    const int wBl = (wN + 255) / 256;
    const int ewBl = (TOTAL / 4 + 255) / 256;
    dim3 cgrid(10, 5, BB * 2);        // px-tiles x py-tiles x (b, co-half)
    dim3 pgrid(80, 8, BB);            // y x ci-slab x b
    dim3 zgrid(82, 4, BB);            // border strips

    zero_border_kernel<<<zgrid, 256>>>(padb);
    prep_w_kernel<<<wBl, 256>>>(w1, (float2*)wtb);
    pad_x_t_kernel<<<pgrid, 256>>>(x, padb);
    // conv1 -> g_h (NCHW)
    conv_mma_kernel<<<cgrid, 256, SMEM>>>(padb, wtb, hb);
    // GN1 stats -> padded relu(gn1(h)) channels-last; prep w2
    gn_stats_kernel<<<BB * GROUPS, 256>>>(hb, meanb, rstdb);
    pad_h_t_kernel<<<pgrid, 256>>>(hb, meanb, rstdb, gn1w, gn1b, padb);
    prep_w_kernel<<<wBl, 256>>>(w2, (float2*)wtb);
    // conv2 -> g_h, GN2 stats
    conv_mma_kernel<<<cgrid, 256, SMEM>>>(padb, wtb, hb);
    gn_stats_kernel<<<BB * GROUPS, 256>>>(hb, meanb, rstdb);
    // gate + fused epilogue
    gate_kernel<<<(BB * HHW) / 256, 256>>>(x, gw, gb, gateb);
    final_kernel<<<ewBl, 256>>>(hb, meanb, rstdb, gn2w, gn2b, gateb, x, out);
}

// round 12
// speedup vs baseline: 2.1266x; 1.6897x over previous
#include <cuda_runtime.h>
#include <cuda_fp16.h>
#include <cstdint>

// ---------------- problem constants ----------------
#define BB 8
#define CC 256
#define HHW 6400          // 80*80
#define GROUPS 32
#define CPG 8
#define TOTAL (BB*CC*HHW) // 13,107,200
#define PW 82
#define PHW (PW*PW)       // 6724
#define NCHUNK 72         // K chunks of 32, tap-major: k = t*256 + ci
#define NSTG 4            // cp.async pipeline stages
#define STAGE 16384       // bytes per stage: A 8KB + B 8KB

// ---------------- scratch (__device__ globals; no allocation) ----------------
__device__ __half g_padh[(size_t)BB * PHW * CC];     // channels-last padded input, fp16
__device__ uint2  g_wtH[(size_t)2 * NCHUNK * 1024];  // weights fp16 fragment-linear
__device__ float  g_h[(size_t)TOTAL];                // conv output, NCHW fp32
__device__ float  g_gate[BB*HHW];
__device__ float  g_mean[BB*GROUPS];
__device__ float  g_rstd[BB*GROUPS];

// ---------------- helpers ----------------
__device__ __forceinline__ void mma_f16(float* d, const uint32_t* a, const uint32_t* b){
    asm volatile(
        "mma.sync.aligned.m16n8k16.row.col.f32.f16.f16.f32 "
        "{%0,%1,%2,%3}, {%4,%5,%6,%7}, {%8,%9}, {%0,%1,%2,%3};"
        : "+f"(d[0]), "+f"(d[1]), "+f"(d[2]), "+f"(d[3])
        : "r"(a[0]), "r"(a[1]), "r"(a[2]), "r"(a[3]), "r"(b[0]), "r"(b[1]));
}
__device__ __forceinline__ void cp_async16(uint32_t dst, const void* src){
    asm volatile("cp.async.cg.shared.global [%0], [%1], 16;" :: "r"(dst), "l"(src));
}
__device__ __forceinline__ void ldmatrix4(uint32_t* r, uint32_t addr){
    asm volatile("ldmatrix.sync.aligned.m8n8.x4.shared.b16 {%0,%1,%2,%3}, [%4];"
        : "=r"(r[0]), "=r"(r[1]), "=r"(r[2]), "=r"(r[3]) : "r"(addr));
}

// ---------------- prep kernels ----------------
// weights -> fp16 B-fragment-linear per (half, chunk):
//   uint2 entry idx = ((half*NCHUNK+ch)*16 + nt)*64 + kt*32 + lane
//   co = half*128 + nt*8 + lane/4 ; kb = (ch&7)*32 + kt*16 ; c = lane%4
//   x = {W[co][kb+2c][t], W[co][kb+2c+1][t]}, y = {.. +8, .. +9}, t = ch>>3
__global__ __launch_bounds__(256)
void prep_w_kernel(const float* __restrict__ w, uint2* __restrict__ wtH)
{
    int i = blockIdx.x * 256 + threadIdx.x;
    if (i >= 2 * NCHUNK * 1024) return;
    int lane = i & 31;
    int kt   = (i >> 5) & 1;
    int nt   = (i >> 6) & 15;
    int rest = i >> 10;                 // half*NCHUNK + ch
    int ch   = rest % NCHUNK;
    int half = rest / NCHUNK;
    int co = half * 128 + nt * 8 + (lane >> 2);
    int t  = ch >> 3;
    int kb = (ch & 7) * 32 + kt * 16 + 2 * (lane & 3);
    const float* wp = w + (size_t)co * CC * 9 + t;
    __half2 lo = __halves2half2(__float2half_rn(wp[(size_t)(kb    ) * 9]),
                                __float2half_rn(wp[(size_t)(kb + 1) * 9]));
    __half2 hi = __halves2half2(__float2half_rn(wp[(size_t)(kb + 8) * 9]),
                                __float2half_rn(wp[(size_t)(kb + 9) * 9]));
    uint2 v;
    v.x = *(uint32_t*)&lo;
    v.y = *(uint32_t*)&hi;
    wtH[i] = v;
}

__global__ __launch_bounds__(256)
void zero_border_kernel(__half* __restrict__ pad)
{
    int pos = blockIdx.x;       // 0..81
    int s   = blockIdx.y;
    int b   = blockIdx.z;
    int py, px;
    if (s == 0)      { py = 0;   px = pos; }
    else if (s == 1) { py = 81;  px = pos; }
    else if (s == 2) { py = pos; px = 0;   }
    else             { py = pos; px = 81;  }
    pad[((size_t)b * PHW + py * PW + px) * CC + threadIdx.x] = __float2half_rn(0.0f);
}

// NCHW x -> channels-last padded fp16 (smem transpose, one row x 32ci per block)
__global__ __launch_bounds__(256)
void pad_x_t_kernel(const float* __restrict__ x, __half* __restrict__ pad)
{
    __shared__ float t[32 * 81];
    const int y   = blockIdx.x;
    const int cB  = blockIdx.y;
    const int b   = blockIdx.z;
    const int tid = threadIdx.x;
    for (int idx = tid; idx < 2560; idx += 256) {
        int px = idx % 80, cc = idx / 80;
        t[cc * 81 + px] = x[((size_t)(b * CC + cB * 32 + cc) * 80 + y) * 80 + px];
    }
    __syncthreads();
    for (int idx = tid; idx < 2560; idx += 256) {
        int cc = idx & 31, px = idx >> 5;
        pad[((size_t)b * PHW + (y + 1) * PW + (px + 1)) * CC + cB * 32 + cc] =
            __float2half_rn(t[cc * 81 + px]);
    }
}

// NCHW h -> GN affine + ReLU -> channels-last padded fp16
__global__ __launch_bounds__(256)
void pad_h_t_kernel(const float* __restrict__ h, const float* __restrict__ mean,
                    const float* __restrict__ rstd, const float* __restrict__ gw,
                    const float* __restrict__ gb, __half* __restrict__ pad)
{
    __shared__ float t[32 * 81];
    __shared__ float ssc[32], ssb[32];
    const int y   = blockIdx.x;
    const int cB  = blockIdx.y;
    const int b   = blockIdx.z;
    const int tid = threadIdx.x;
    if (tid < 32) {
        int ci = cB * 32 + tid;
        int bg = b * GROUPS + ci / CPG;
        float sc = rstd[bg] * gw[ci];
        ssc[tid] = sc;
        ssb[tid] = fmaf(-mean[bg], sc, gb[ci]);
    }
    for (int idx = tid; idx < 2560; idx += 256) {
        int px = idx % 80, cc = idx / 80;
        t[cc * 81 + px] = h[((size_t)(b * CC + cB * 32 + cc) * 80 + y) * 80 + px];
    }
    __syncthreads();
    for (int idx = tid; idx < 2560; idx += 256) {
        int cc = idx & 31, px = idx >> 5;
        float v = fmaxf(fmaf(t[cc * 81 + px], ssc[cc], ssb[cc]), 0.0f);
        pad[((size_t)b * PHW + (y + 1) * PW + (px + 1)) * CC + cB * 32 + cc] =
            __float2half_rn(v);
    }
}

// ---------------- fp16 HMMA implicit-GEMM conv, cp.async 4-stage ----------------
// 256 thr = 8 warps (2M x 4N), warp tile 64px x 32co. CTA tile 128px x 128co.
// Pixel tile 16 rows x 8 cols. K chunk = 32 (one tap, 32 contiguous ci).
// Stage: A plane-major [kk(4)][px(128)][16B] 8KB + B fragment-linear 8KB.
__global__ __launch_bounds__(256, 2)
void conv_mma_kernel(const __half* __restrict__ pad, const uint2* __restrict__ wtH,
                     float* __restrict__ out)
{
    extern __shared__ char dsm[];
    __shared__ int s_toff[9];

    const int tid  = threadIdx.x;
    const int lane = tid & 31;
    const int warp = tid >> 5;               // 0..7
    const int mw = warp >> 2;                // 0..1
    const int nw = warp & 3;                 // 0..3

    if (tid < 9) s_toff[tid] = ((tid / 3) * PW + (tid % 3)) * CC;

    const int PX0 = blockIdx.x * 8;
    const int PY0 = blockIdx.y * 16;
    const int bz  = blockIdx.z;
    const int b   = bz >> 1;
    const int half = bz & 1;
    const int co0  = half * 128;

    // producer: thread covers pixel pxP = tid>>1, k-half segH = tid&1
    const int pxP  = tid >> 1;
    const int segH = tid & 1;
    const int gy = PY0 + (pxP >> 3);
    const int gx = PX0 + (pxP & 7);
    const __half* Apix = pad + ((size_t)b * PHW + (size_t)gy * PW + gx) * CC;
    const char* Bsrc0 = (const char*)(wtH + (size_t)half * NCHUNK * 1024);
    const uint32_t smem0 = (uint32_t)__cvta_generic_to_shared(dsm);

    // consumer ldmatrix lane address part: tile t = lane>>3, row w = lane&7
    const int ltile = lane >> 3;
    const uint32_t lmLane = (uint32_t)((ltile >> 1) * 2048 +
                                       (((ltile & 1) * 8 + (lane & 7)) * 16));

    float acc[4][4][4];
#pragma unroll
    for (int mi = 0; mi < 4; mi++)
#pragma unroll
        for (int ni = 0; ni < 4; ni++)
#pragma unroll
            for (int q = 0; q < 4; q++) acc[mi][ni][q] = 0.0f;

    __syncthreads();   // s_toff ready

#define ISSUE(CH) do {                                                          \
        const int _ch = (CH);                                                   \
        const int _st = _ch & (NSTG - 1);                                       \
        const __half* _as = Apix + s_toff[_ch >> 3] + ((_ch & 7) << 5);         \
        uint32_t _base = smem0 + _st * STAGE;                                   \
        _Pragma("unroll")                                                       \
        for (int _j = 0; _j < 2; _j++) {                                        \
            int _kk = segH * 2 + _j;                                            \
            cp_async16(_base + _kk * 2048 + pxP * 16, _as + _kk * 8);           \
        }                                                                       \
        const char* _bs = Bsrc0 + (size_t)_ch * 8192 + tid * 32;                \
        uint32_t _bd = _base + 8192 + tid * 32;                                 \
        cp_async16(_bd,      _bs);                                              \
        cp_async16(_bd + 16, _bs + 16);                                         \
        asm volatile("cp.async.commit_group;" ::: "memory");                    \
    } while (0)

    // prologue: stages 0..2
    ISSUE(0);
    ISSUE(1);
    ISSUE(2);

    for (int ch = 0; ch < NCHUNK; ch++) {
        if (ch < NCHUNK - 3)
            asm volatile("cp.async.wait_group 2;" ::: "memory");
        else if (ch == NCHUNK - 3)
            asm volatile("cp.async.wait_group 2;" ::: "memory");
        else if (ch == NCHUNK - 2)
            asm volatile("cp.async.wait_group 1;" ::: "memory");
        else
            asm volatile("cp.async.wait_group 0;" ::: "memory");
        __syncthreads();

        const int st = ch & (NSTG - 1);
        const uint32_t Abase = smem0 + st * STAGE;
        const uint2* Bs = (const uint2*)(dsm + st * STAGE + 8192);

#pragma unroll
        for (int kt = 0; kt < 2; kt++) {
            uint32_t af[4][4];
            uint2 bf[4];
            const uint32_t kbase = Abase + kt * 4096 + lmLane;
#pragma unroll
            for (int mi = 0; mi < 4; mi++)
                ldmatrix4(af[mi], kbase + (uint32_t)((mw * 64 + mi * 16) * 16));
#pragma unroll
            for (int ni = 0; ni < 4; ni++)
                bf[ni] = Bs[(nw * 4 + ni) * 64 + kt * 32 + lane];
#pragma unroll
            for (int mi = 0; mi < 4; mi++)
#pragma unroll
                for (int ni = 0; ni < 4; ni++)
                    mma_f16(acc[mi][ni], af[mi], (const uint32_t*)&bf[ni]);
        }

        if (ch + 3 < NCHUNK) ISSUE(ch + 3);
    }
#undef ISSUE

    // ---- epilogue: acc -> out[b][co][py][px] (NCHW) ----
    // d-frag: d0=D[m][c], d1=D[m][c+1], d2=D[m+8][c], d3=D[m+8][c+1]
    const int r0 = lane >> 2;
    const int c0 = 2 * (lane & 3);
#pragma unroll
    for (int mi = 0; mi < 4; mi++) {
        int gpy = PY0 + mw * 8 + mi * 2;
        int gxx = PX0 + r0;
#pragma unroll
        for (int ni = 0; ni < 4; ni++) {
            int co_c = co0 + nw * 32 + ni * 8 + c0;
            float* p = out + ((size_t)b * CC + co_c) * HHW + gpy * 80 + gxx;
            p[0]        = acc[mi][ni][0];
            p[HHW]      = acc[mi][ni][1];
            p[80]       = acc[mi][ni][2];
            p[HHW + 80] = acc[mi][ni][3];
        }
    }
}

// ---------------- GroupNorm stats ----------------
__global__ __launch_bounds__(256)
void gn_stats_kernel(const float* __restrict__ in, float* __restrict__ mean,
                     float* __restrict__ rstd)
{
    const int bg = blockIdx.x;
    const float4* p = (const float4*)(in + (size_t)bg * (CPG * HHW));
    const int tid = threadIdx.x;
    float s = 0.0f, ss = 0.0f;
#pragma unroll 4
    for (int i = tid; i < CPG * HHW / 4; i += 256) {
        float4 v = p[i];
        s += v.x + v.y + v.z + v.w;
        ss = fmaf(v.x, v.x, ss); ss = fmaf(v.y, v.y, ss);
        ss = fmaf(v.z, v.z, ss); ss = fmaf(v.w, v.w, ss);
    }
    __shared__ float sb0[8], sb1[8];
#pragma unroll
    for (int o = 16; o; o >>= 1) {
        s  += __shfl_down_sync(0xffffffffu, s, o);
        ss += __shfl_down_sync(0xffffffffu, ss, o);
    }
    if ((tid & 31) == 0) { sb0[tid >> 5] = s; sb1[tid >> 5] = ss; }
    __syncthreads();
    if (tid == 0) {
        s = 0.0f; ss = 0.0f;
#pragma unroll
        for (int i = 0; i < 8; i++) { s += sb0[i]; ss += sb1[i]; }
        const float inv_n = 1.0f / (float)(CPG * HHW);
        float m = s * inv_n;
        float var = ss * inv_n - m * m;
        mean[bg] = m;
        rstd[bg] = rsqrtf(var + 1e-5f);
    }
}

// ---------------- spatial gate ----------------
__global__ __launch_bounds__(256)
void gate_kernel(const float* __restrict__ x, const float* __restrict__ gw,
                 const float* __restrict__ gb, float* __restrict__ gate)
{
    __shared__ float wsm[CC];
    const int tid = threadIdx.x;
    wsm[tid] = gw[tid];
    __syncthreads();
    const int p = blockIdx.x * 256 + tid;
    const int b = p / HHW, pp = p - b * HHW;
    const float* xb = x + (size_t)b * CC * HHW + pp;
    float s = gb[0];
#pragma unroll 8
    for (int c = 0; c < CC; c++) s = fmaf(xb[(size_t)c * HHW], wsm[c], s);
    gate[p] = fmaxf(tanhf(s), 0.0f);
}

// ---------------- final: out = relu(gn2(h)*gate + x) ----------------
__global__ __launch_bounds__(256)
void final_kernel(const float* __restrict__ h, const float* __restrict__ mean,
                  const float* __restrict__ rstd, const float* __restrict__ w,
                  const float* __restrict__ bias, const float* __restrict__ gate,
                  const float* __restrict__ x, float* __restrict__ out)
{
    int idx = blockIdx.x * blockDim.x + threadIdx.x;
    if (idx >= TOTAL / 4) return;
    const int c  = (idx / (HHW / 4)) % CC;
    const int b  = idx / ((HHW / 4) * CC);
    const int bg = b * GROUPS + c / CPG;
    const float sc = rstd[bg] * w[c];
    const float sb = fmaf(-mean[bg], sc, bias[c]);
    const int p4 = idx % (HHW / 4);
    const float4 g4 = ((const float4*)(gate + (size_t)b * HHW))[p4];
    float4 hv = ((const float4*)h)[idx];
    float4 xv = ((const float4*)x)[idx];
    float4 o;
    o.x = fmaxf(fmaf(fmaf(hv.x, sc, sb), g4.x, xv.x), 0.0f);
    o.y = fmaxf(fmaf(fmaf(hv.y, sc, sb), g4.y, xv.y), 0.0f);
    o.z = fmaxf(fmaf(fmaf(hv.z, sc, sb), g4.z, xv.z), 0.0f);
    o.w = fmaxf(fmaf(fmaf(hv.w, sc, sb), g4.w, xv.w), 0.0f);
    ((float4*)out)[idx] = o;
}

// ---------------- launch ----------------
extern "C" void kernel_launch(void* const* d_in, const int* in_sizes, int n_in,
                              void* d_out, int out_size)
{
    const float* x    = (const float*)d_in[0];
    const float* w1   = (const float*)d_in[1];
    const float* gn1w = (const float*)d_in[2];
    const float* gn1b = (const float*)d_in[3];
    const float* w2   = (const float*)d_in[4];
    const float* gn2w = (const float*)d_in[5];
    const float* gn2b = (const float*)d_in[6];
    const float* gw   = (const float*)d_in[7];
    const float* gb   = (const float*)d_in[8];
    float* out = (float*)d_out;

    __half* padb; uint2* wtb; float *hb, *gateb, *meanb, *rstdb;
    cudaGetSymbolAddress((void**)&padb,  g_padh);
    cudaGetSymbolAddress((void**)&wtb,   g_wtH);
    cudaGetSymbolAddress((void**)&hb,    g_h);
    cudaGetSymbolAddress((void**)&gateb, g_gate);
    cudaGetSymbolAddress((void**)&meanb, g_mean);
    cudaGetSymbolAddress((void**)&rstdb, g_rstd);

    const int SMEM = NSTG * STAGE;   // 64 KB
    cudaFuncSetAttribute(conv_mma_kernel,
                         cudaFuncAttributeMaxDynamicSharedMemorySize, SMEM);

    const int wN  = 2 * NCHUNK * 1024;
    const int wBl = (wN + 255) / 256;
    const int ewBl = (TOTAL / 4 + 255) / 256;
    dim3 cgrid(10, 5, BB * 2);        // px-tiles x py-tiles x (b, co-half)
    dim3 pgrid(80, 8, BB);            // y x ci-slab x b
    dim3 zgrid(82, 4, BB);            // border strips

    zero_border_kernel<<<zgrid, 256>>>(padb);
    prep_w_kernel<<<wBl, 256>>>(w1, wtb);
    pad_x_t_kernel<<<pgrid, 256>>>(x, padb);
    // conv1 -> g_h (NCHW fp32)
    conv_mma_kernel<<<cgrid, 256, SMEM>>>(padb, wtb, hb);
    // GN1 stats -> padded relu(gn1(h)) channels-last fp16; prep w2
    gn_stats_kernel<<<BB * GROUPS, 256>>>(hb, meanb, rstdb);
    pad_h_t_kernel<<<pgrid, 256>>>(hb, meanb, rstdb, gn1w, gn1b, padb);
    prep_w_kernel<<<wBl, 256>>>(w2, wtb);
    // conv2 -> g_h, GN2 stats
    conv_mma_kernel<<<cgrid, 256, SMEM>>>(padb, wtb, hb);
    gn_stats_kernel<<<BB * GROUPS, 256>>>(hb, meanb, rstdb);
    // gate + fused epilogue
    gate_kernel<<<(BB * HHW) / 256, 256>>>(x, gw, gb, gateb);
    final_kernel<<<ewBl, 256>>>(hb, meanb, rstdb, gn2w, gn2b, gateb, x, out);
}